// round 6
// baseline (speedup 1.0000x reference)
#include <cuda_runtime.h>
#include <cuda_bf16.h>
#include <math.h>

#define Bb 32
#define Ss 512
#define Hh 1024
#define Mm 8
#define NTOK (Bb * Ss)       // 16384
#define NSPAN (NTOK * Mm)    // 131072
#define TOPK 4915            // int(0.3 * B * S)
#define NBIN 65536
#define NCHUNK 1024          // 64 bins per chunk
#define TIE_CAP 16384
#define CF_BLOCKS 148
#define CF_THREADS 256
#define TPB 32               // tokens per block in k_efs
#define NTASK 39             // 32 tokens + 7 halo rows

// ---------------- device scratch ----------------
__device__ float g_query[Hh];
__device__ unsigned int g_keys[NSPAN];
__device__ int   g_hist16[NBIN];
__device__ unsigned char g_gbits[NTOK];   // bit l of byte t: span (t,l) valid&&gold
__device__ float g_sp_sum;
__device__ int   g_gold_cnt;
__device__ int   g_valid_cnt;
__device__ unsigned int g_selP;
__device__ int   g_selRem;
__device__ int   g_right;
__device__ int   g_tiecnt;
__device__ int   g_done;      // for k_count_final
__device__ int   g_done_ef;   // for k_efs last-block
__device__ int   g_tie[TIE_CAP];

__device__ __forceinline__ float warpReduceF(float v) {
    #pragma unroll
    for (int o = 16; o; o >>= 1) v += __shfl_xor_sync(0xffffffffu, v, o);
    return v;
}
__device__ __forceinline__ int warpReduceI(int v) {
    #pragma unroll
    for (int o = 16; o; o >>= 1) v += __shfl_xor_sync(0xffffffffu, v, o);
    return v;
}

// ---------------- kernel 1: query = w_in @ term_weight + b_in; init + zero hist ------------
__global__ void k_query(const float* __restrict__ w_in,
                        const float* __restrict__ tw,
                        const float* __restrict__ b_in) {
    int r = blockIdx.x;
    int gid = blockIdx.x * blockDim.x + threadIdx.x;
    if (gid == 0) {
        g_sp_sum = 0.0f; g_gold_cnt = 0; g_valid_cnt = 0;
        g_right = 0; g_tiecnt = 0; g_done = 0; g_done_ef = 0;
    }
    if (gid < NBIN) g_hist16[gid] = 0;

    const float4* wr = reinterpret_cast<const float4*>(w_in + (size_t)r * Hh);
    const float4* t4 = reinterpret_cast<const float4*>(tw);
    int i = threadIdx.x;
    float4 a = wr[i];
    float4 b = t4[i];
    float acc = a.x * b.x + a.y * b.y + a.z * b.z + a.w * b.w;

    __shared__ float sh[8];
    float v = warpReduceF(acc);
    if ((threadIdx.x & 31) == 0) sh[threadIdx.x >> 5] = v;
    __syncthreads();
    if (threadIdx.x < 8) {
        float x = sh[threadIdx.x];
        #pragma unroll
        for (int o = 4; o; o >>= 1) x += __shfl_xor_sync(0xffu, x, o);
        if (threadIdx.x == 0) g_query[r] = x + b_in[r];
    }
}

// ---------------- kernel 2: fused e/f + scores + hist; last block does reduce+scan --------
__global__ void __launch_bounds__(1024, 1)
k_efs(const float* __restrict__ hidden,
      const float* __restrict__ score_w,
      const float* __restrict__ score_b_p,
      const int* __restrict__ seq_len,
      const int* __restrict__ gold_mask) {
    __shared__ float shq[Hh];
    __shared__ float shw[Hh];
    __shared__ float she[NTASK];
    __shared__ float shfv[NTASK];
    __shared__ int   sch[NCHUNK];
    __shared__ int   s_bchunk, s_above;
    __shared__ int   s_bins[64];
    __shared__ bool  s_last;

    int tid = threadIdx.x, warp = tid >> 5, lane = tid & 31;
    int t0 = blockIdx.x * TPB;           // first token of this block
    int s0 = t0 & (Ss - 1);
    int bb = t0 >> 9;                    // batch index (constant per block: 32 | 512)
    int nt = Ss - s0; if (nt > NTASK) nt = NTASK;   // tasks (rows) this block computes

    for (int i = tid; i < Hh; i += 1024) {
        shq[i] = g_query[i];
        shw[i] = score_w[i];
    }
    __syncthreads();

    // ---- e/f for nt rows (warp-per-row, second pass for halo rows) ----
    for (int w = warp; w < nt; w += 32) {
        const float4* hp = reinterpret_cast<const float4*>(hidden + (size_t)(t0 + w) * Hh);
        float e = 0.0f, f = 0.0f;
        #pragma unroll
        for (int c = 0; c < 8; c++) {
            int j = c * 32 + lane;
            float4 h = hp[j];
            int k = j * 4;
            e += h.x * shq[k] + h.y * shq[k + 1] + h.z * shq[k + 2] + h.w * shq[k + 3];
            f += h.x * shw[k] + h.y * shw[k + 1] + h.z * shw[k + 2] + h.w * shw[k + 3];
        }
        e = warpReduceF(e);
        f = warpReduceF(f);
        if (lane == 0) { she[w] = e; shfv[w] = f; }
    }
    __syncthreads();

    // ---- score phase: warp 0, one token per lane ----
    if (warp == 0) {
        int i = lane;
        int t = t0 + i, s = s0 + i;
        int L = seq_len[bb];
        float sb = score_b_p[0];

        const int4* gm4 = reinterpret_cast<const int4*>(gold_mask + t * Mm);
        int4 gm0 = gm4[0], gm1 = gm4[1];
        int gm[8] = {gm0.x, gm0.y, gm0.z, gm0.w, gm1.x, gm1.y, gm1.z, gm1.w};

        float m = -INFINITY, den = 0.0f, num = 0.0f;
        unsigned keys[8];
        unsigned char gb = 0;
        float sp_local = 0.0f;
        int gold_local = 0, valid_local = 0;

        #pragma unroll
        for (int l = 0; l < Mm; l++) {
            int idx = i + l; if (idx > nt - 1) idx = nt - 1;   // clip at row end (== clip pos at S-1)
            float el = she[idx];
            float fl = shfv[idx];
            float mn = fmaxf(m, el);
            float sc = expf(m - mn);
            float we = expf(el - mn);
            den = den * sc + we;
            num = num * sc + we * fl;
            m = mn;
            float score = num / den + sb;

            unsigned key;
            if (s + l + 1 <= L) {
                unsigned u = __float_as_uint(score);
                key = u ^ ((u >> 31) ? 0xFFFFFFFFu : 0x80000000u);
                valid_local++;
                if (gm[l] == 0) {
                    gold_local++;
                    gb |= (unsigned char)(1u << l);
                    sp_local += fmaxf(-score, 0.0f) + log1pf(expf(-fabsf(score)));
                }
            } else {
                key = 0x007FFFFFu;  // flipped -inf
            }
            keys[l] = key;
            atomicAdd(&g_hist16[key >> 16], 1);
        }
        uint4* kp = reinterpret_cast<uint4*>(g_keys + t * Mm);
        kp[0] = make_uint4(keys[0], keys[1], keys[2], keys[3]);
        kp[1] = make_uint4(keys[4], keys[5], keys[6], keys[7]);
        g_gbits[t] = gb;

        float sp = warpReduceF(sp_local);
        int gd = warpReduceI(gold_local);
        int vd = warpReduceI(valid_local);
        if (lane == 0) {
            atomicAdd(&g_sp_sum, sp);
            atomicAdd(&g_gold_cnt, gd);
            atomicAdd(&g_valid_cnt, vd);
        }
    }

    // ---- last-block: histogram reduce + suffix scan + boundary walk ----
    __threadfence();
    __syncthreads();
    if (tid == 0) {
        int d = atomicAdd(&g_done_ef, 1);
        s_last = (d == (int)gridDim.x - 1);
    }
    __syncthreads();
    if (!s_last) return;

    const int4* h4 = reinterpret_cast<const int4*>(g_hist16);
    #pragma unroll 2
    for (int j = 0; j < 16; j++) {
        int4 v = h4[j * 1024 + tid];                 // coalesced
        int sgr = v.x + v.y + v.z + v.w;
        #pragma unroll
        for (int o = 8; o; o >>= 1) sgr += __shfl_xor_sync(0xffffffffu, sgr, o);
        if ((tid & 15) == 0) sch[j * 64 + (tid >> 4)] = sgr;
    }
    __syncthreads();
    int csum = sch[tid];
    for (int off = 1; off < NCHUNK; off <<= 1) {
        int v = (tid + off < NCHUNK) ? sch[tid + off] : 0;
        __syncthreads();
        sch[tid] += v;
        __syncthreads();
    }
    int incl = sch[tid];
    int above = incl - csum;
    if (above < TOPK && incl >= TOPK) { s_bchunk = tid; s_above = above; }
    __syncthreads();
    int bc = s_bchunk;
    if (tid < 64) s_bins[tid] = g_hist16[bc * 64 + tid];
    __syncthreads();
    if (tid == 0) {
        int cum = s_above;
        for (int b = 63; b >= 0; b--) {
            int c = s_bins[b];
            if (cum + c >= TOPK) {
                g_selP = (unsigned)(bc * 64 + b);
                g_selRem = TOPK - cum;
                break;
            }
            cum += c;
        }
    }
}

// ---------------- kernel 3: count above threshold + ties; last block finalizes ------------
__global__ void k_count_final(float* __restrict__ out) {
    unsigned P = g_selP;
    int tid = blockIdx.x * blockDim.x + threadIdx.x;
    int nthreads = gridDim.x * blockDim.x;
    int gg = 0;
    for (int i = tid; i < NSPAN; i += nthreads) {
        unsigned top = g_keys[i] >> 16;
        if (top > P) {
            if ((g_gbits[i >> 3] >> (i & 7)) & 1) gg++;
        } else if (top == P) {
            int pos = atomicAdd(&g_tiecnt, 1);
            if (pos < TIE_CAP) g_tie[pos] = i;
        }
    }
    gg = warpReduceI(gg);
    __shared__ int shc[8];
    __shared__ bool s_last;
    if ((threadIdx.x & 31) == 0) shc[threadIdx.x >> 5] = gg;
    __threadfence();
    __syncthreads();
    if (threadIdx.x == 0) {
        int S = 0;
        #pragma unroll
        for (int w = 0; w < (CF_THREADS >> 5); w++) S += shc[w];
        if (S) atomicAdd(&g_right, S);
        __threadfence();
        int d = atomicAdd(&g_done, 1);
        s_last = (d == (int)gridDim.x - 1);
    }
    __syncthreads();
    if (!s_last) return;

    // ---- final phase: only last block ----
    int n = g_tiecnt; if (n > TIE_CAP) n = TIE_CAP;
    int rem = g_selRem;
    __shared__ int s_g;
    if (threadIdx.x == 0) s_g = 0;
    __syncthreads();

    int gtie = 0;
    for (int j = threadIdx.x; j < n; j += blockDim.x) {
        int ij = g_tie[j];
        unsigned kj = g_keys[ij];
        int rank = 0;
        for (int q = 0; q < n; q++) {
            int iq = g_tie[q];
            unsigned kq = g_keys[iq];
            if (kq > kj || (kq == kj && iq < ij)) rank++;
        }
        if (rank < rem) {
            if ((g_gbits[ij >> 3] >> (ij & 7)) & 1) gtie++;
        }
    }
    gtie = warpReduceI(gtie);
    if ((threadIdx.x & 31) == 0 && gtie) atomicAdd(&s_g, gtie);
    __syncthreads();

    if (threadIdx.x == 0) {
        int right = g_right + s_g;
        float nv = (float)g_valid_cnt;
        float loss = (g_sp_sum + 0.6931471805599453f * (float)(g_valid_cnt - g_gold_cnt)) / nv;
        out[0] = loss;
        out[1] = (float)right / (float)TOPK;
    }
}

// ---------------- launch ----------------
extern "C" void kernel_launch(void* const* d_in, const int* in_sizes, int n_in,
                              void* d_out, int out_size) {
    const float* hidden  = (const float*)d_in[0];
    const float* tw      = (const float*)d_in[1];
    const float* w_in    = (const float*)d_in[2];
    const float* b_in    = (const float*)d_in[3];
    const float* score_w = (const float*)d_in[4];
    const float* score_b = (const float*)d_in[5];
    const int*   seq_len = (const int*)d_in[6];
    const int*   gold    = (const int*)d_in[7];
    float* out = (float*)d_out;

    k_query      <<<Hh, 256>>>(w_in, tw, b_in);
    k_efs        <<<NTOK / TPB, 1024>>>(hidden, score_w, score_b, seq_len, gold);
    k_count_final<<<CF_BLOCKS, CF_THREADS>>>(out);
}

// round 7
// speedup vs baseline: 1.2733x; 1.2733x over previous
#include <cuda_runtime.h>
#include <cuda_bf16.h>
#include <math.h>

#define Bb 32
#define Ss 512
#define Hh 1024
#define Mm 8
#define NTOK (Bb * Ss)       // 16384
#define NSPAN (NTOK * Mm)    // 131072
#define TOPK 4915            // int(0.3 * B * S)
#define NBIN 65536
#define NCOARSE 1024         // coarse bins: key >> 22
#define TIE_CAP 16384
#define CF_BLOCKS 148
#define CF_THREADS 256

// ---------------- device scratch ----------------
__device__ float g_query[Hh];
__device__ float g_e[NTOK];
__device__ float g_f[NTOK];
__device__ unsigned int g_keys[NSPAN];
__device__ int   g_hist16[NBIN];
__device__ int   g_coarse[NCOARSE];
__device__ unsigned char g_gbits[NTOK];   // bit l of byte t: span (t,l) valid&&gold
__device__ float g_sp_sum;
__device__ int   g_gold_cnt;
__device__ int   g_valid_cnt;
__device__ unsigned int g_selP;
__device__ int   g_selRem;
__device__ int   g_right;
__device__ int   g_tiecnt;
__device__ int   g_done;      // for k_count_final
__device__ int   g_done_sc;   // for k_scores last-block
__device__ int   g_tie[TIE_CAP];

__device__ __forceinline__ float warpReduceF(float v) {
    #pragma unroll
    for (int o = 16; o; o >>= 1) v += __shfl_xor_sync(0xffffffffu, v, o);
    return v;
}
__device__ __forceinline__ int warpReduceI(int v) {
    #pragma unroll
    for (int o = 16; o; o >>= 1) v += __shfl_xor_sync(0xffffffffu, v, o);
    return v;
}

// ---------------- kernel 1: query = w_in @ term_weight + b_in; init + zero hists ----------
// 128 blocks x 1024 threads; 8 rows per block, 128 threads/row, 2 float4 per thread.
__global__ void k_query(const float* __restrict__ w_in,
                        const float* __restrict__ tw,
                        const float* __restrict__ b_in) {
    __shared__ float shtw[Hh];
    __shared__ float part[32];   // 8 rows x 4 warps-per-row
    int tid = threadIdx.x;
    int gid = blockIdx.x * 1024 + tid;
    if (gid == 0) {
        g_sp_sum = 0.0f; g_gold_cnt = 0; g_valid_cnt = 0;
        g_right = 0; g_tiecnt = 0; g_done = 0; g_done_sc = 0;
    }
    if (gid < NBIN) g_hist16[gid] = 0;       // 131072 threads cover 65536
    if (gid < NCOARSE) g_coarse[gid] = 0;
    for (int i = tid; i < Hh; i += 1024) shtw[i] = tw[i];
    __syncthreads();

    int rloc = tid >> 7;                      // row in block: 0..7
    int r = blockIdx.x * 8 + rloc;
    int c = tid & 127;                        // float4 lane in row
    const float4* wr = reinterpret_cast<const float4*>(w_in + (size_t)r * Hh);
    const float4* t4 = reinterpret_cast<const float4*>(shtw);
    float4 a0 = wr[c],       a1 = wr[c + 128];
    float4 b0 = t4[c],       b1 = t4[c + 128];
    float acc = a0.x * b0.x + a0.y * b0.y + a0.z * b0.z + a0.w * b0.w
              + a1.x * b1.x + a1.y * b1.y + a1.z * b1.z + a1.w * b1.w;
    acc = warpReduceF(acc);
    if ((tid & 31) == 0) part[tid >> 5] = acc;   // part[rloc*4 + warpInRow]
    __syncthreads();
    if (tid < 8) {
        float x = part[tid * 4] + part[tid * 4 + 1] + part[tid * 4 + 2] + part[tid * 4 + 3];
        g_query[blockIdx.x * 8 + tid] = x + b_in[blockIdx.x * 8 + tid];
    }
}

// ---------------- kernel 2: e/f dot products (DRAM-bound 64MB pass) ----------------
__global__ void k_ef(const float* __restrict__ hidden,
                     const float* __restrict__ score_w) {
    __shared__ float shq[Hh];
    __shared__ float shw[Hh];
    for (int i = threadIdx.x; i < Hh; i += blockDim.x) {
        shq[i] = g_query[i];
        shw[i] = score_w[i];
    }
    __syncthreads();

    int warp = threadIdx.x >> 5, lane = threadIdx.x & 31;
    int t = blockIdx.x * 8 + warp;
    const float4* hp = reinterpret_cast<const float4*>(hidden + (size_t)t * Hh);
    float e = 0.0f, f = 0.0f;
    #pragma unroll
    for (int c = 0; c < 8; c++) {
        int j = c * 32 + lane;
        float4 h = hp[j];
        int k = j * 4;
        e += h.x * shq[k] + h.y * shq[k + 1] + h.z * shq[k + 2] + h.w * shq[k + 3];
        f += h.x * shw[k] + h.y * shw[k + 1] + h.z * shw[k + 2] + h.w * shw[k + 3];
    }
    e = warpReduceF(e);
    f = warpReduceF(f);
    if (lane == 0) { g_e[t] = e; g_f[t] = f; }
}

// ---------------- kernel 3: scores + keys + gbits + dual hist; last block selects ---------
// 16 blocks x 1024 threads, one token per thread.
__global__ void k_scores(const float* __restrict__ score_b_p,
                         const int* __restrict__ seq_len,
                         const int* __restrict__ gold_mask) {
    __shared__ float shf[32];
    __shared__ int shg[32], shv[32];
    __shared__ int sch[NCOARSE];
    __shared__ int s_bchunk, s_above;
    __shared__ int s_bins[64];
    __shared__ bool s_last;

    int tid = threadIdx.x;
    int t = blockIdx.x * 1024 + tid;
    int b = t >> 9, s = t & (Ss - 1);
    int L = seq_len[b];
    float sb = score_b_p[0];

    const int4* gm4 = reinterpret_cast<const int4*>(gold_mask + t * Mm);
    int4 gm0 = gm4[0], gm1 = gm4[1];
    int gm[8] = {gm0.x, gm0.y, gm0.z, gm0.w, gm1.x, gm1.y, gm1.z, gm1.w};

    float m = -INFINITY, den = 0.0f, num = 0.0f;
    unsigned keys[8];
    unsigned char gb = 0;
    float sp_local = 0.0f;
    int gold_local = 0, valid_local = 0;

    #pragma unroll
    for (int l = 0; l < Mm; l++) {
        int pos = s + l; if (pos > Ss - 1) pos = Ss - 1;
        float el = g_e[(b << 9) + pos];
        float fl = g_f[(b << 9) + pos];
        float mn = fmaxf(m, el);
        float sc = expf(m - mn);
        float we = expf(el - mn);
        den = den * sc + we;
        num = num * sc + we * fl;
        m = mn;
        float score = num / den + sb;

        unsigned key;
        if (s + l + 1 <= L) {
            unsigned u = __float_as_uint(score);
            key = u ^ ((u >> 31) ? 0xFFFFFFFFu : 0x80000000u);
            valid_local++;
            if (gm[l] == 0) {
                gold_local++;
                gb |= (unsigned char)(1u << l);
                sp_local += fmaxf(-score, 0.0f) + log1pf(expf(-fabsf(score)));
            }
        } else {
            key = 0x007FFFFFu;  // flipped -inf
        }
        keys[l] = key;
        atomicAdd(&g_hist16[key >> 16], 1);
        atomicAdd(&g_coarse[key >> 22], 1);
    }
    uint4* kp = reinterpret_cast<uint4*>(g_keys + t * Mm);
    kp[0] = make_uint4(keys[0], keys[1], keys[2], keys[3]);
    kp[1] = make_uint4(keys[4], keys[5], keys[6], keys[7]);
    g_gbits[t] = gb;

    float sp = warpReduceF(sp_local);
    int gd = warpReduceI(gold_local);
    int vd = warpReduceI(valid_local);
    if ((tid & 31) == 0) {
        int w = tid >> 5;
        shf[w] = sp; shg[w] = gd; shv[w] = vd;
    }
    __syncthreads();
    if (tid == 0) {
        float S1 = 0.0f; int S2 = 0, S3 = 0;
        #pragma unroll
        for (int w = 0; w < 32; w++) { S1 += shf[w]; S2 += shg[w]; S3 += shv[w]; }
        atomicAdd(&g_sp_sum, S1);
        atomicAdd(&g_gold_cnt, S2);
        atomicAdd(&g_valid_cnt, S3);
    }

    // ---- last-block tail: coarse scan + fine walk ----
    __threadfence();
    __syncthreads();
    if (tid == 0) {
        int d = atomicAdd(&g_done_sc, 1);
        s_last = (d == (int)gridDim.x - 1);
    }
    __syncthreads();
    if (!s_last) return;

    int csum = g_coarse[tid];                 // 4KB coalesced
    sch[tid] = csum;
    __syncthreads();
    for (int off = 1; off < NCOARSE; off <<= 1) {
        int v = (tid + off < NCOARSE) ? sch[tid + off] : 0;
        __syncthreads();
        sch[tid] += v;
        __syncthreads();
    }
    int incl = sch[tid];
    int above = incl - csum;
    if (above < TOPK && incl >= TOPK) { s_bchunk = tid; s_above = above; }
    __syncthreads();
    int bc = s_bchunk;
    if (tid < 64) s_bins[tid] = g_hist16[bc * 64 + tid];   // fine bins of boundary coarse bin
    __syncthreads();
    if (tid == 0) {
        int cum = s_above;
        for (int bn = 63; bn >= 0; bn--) {
            int c = s_bins[bn];
            if (cum + c >= TOPK) {
                g_selP = (unsigned)(bc * 64 + bn);
                g_selRem = TOPK - cum;
                break;
            }
            cum += c;
        }
    }
}

// ---------------- kernel 4: count above threshold + ties; last block finalizes ------------
__global__ void k_count_final(float* __restrict__ out) {
    unsigned P = g_selP;
    int tid = blockIdx.x * blockDim.x + threadIdx.x;
    int nthreads = gridDim.x * blockDim.x;
    int gg = 0;
    for (int i = tid; i < NSPAN; i += nthreads) {
        unsigned top = g_keys[i] >> 16;
        if (top > P) {
            if ((g_gbits[i >> 3] >> (i & 7)) & 1) gg++;
        } else if (top == P) {
            int pos = atomicAdd(&g_tiecnt, 1);
            if (pos < TIE_CAP) g_tie[pos] = i;
        }
    }
    gg = warpReduceI(gg);
    __shared__ int shc[8];
    __shared__ bool s_last;
    if ((threadIdx.x & 31) == 0) shc[threadIdx.x >> 5] = gg;
    __threadfence();
    __syncthreads();
    if (threadIdx.x == 0) {
        int S = 0;
        #pragma unroll
        for (int w = 0; w < (CF_THREADS >> 5); w++) S += shc[w];
        if (S) atomicAdd(&g_right, S);
        __threadfence();
        int d = atomicAdd(&g_done, 1);
        s_last = (d == (int)gridDim.x - 1);
    }
    __syncthreads();
    if (!s_last) return;

    // ---- final phase: only last block ----
    int n = g_tiecnt; if (n > TIE_CAP) n = TIE_CAP;
    int rem = g_selRem;
    __shared__ int s_g;
    if (threadIdx.x == 0) s_g = 0;
    __syncthreads();

    int gtie = 0;
    for (int j = threadIdx.x; j < n; j += blockDim.x) {
        int ij = g_tie[j];
        unsigned kj = g_keys[ij];
        int rank = 0;
        for (int q = 0; q < n; q++) {
            int iq = g_tie[q];
            unsigned kq = g_keys[iq];
            if (kq > kj || (kq == kj && iq < ij)) rank++;
        }
        if (rank < rem) {
            if ((g_gbits[ij >> 3] >> (ij & 7)) & 1) gtie++;
        }
    }
    gtie = warpReduceI(gtie);
    if ((threadIdx.x & 31) == 0 && gtie) atomicAdd(&s_g, gtie);
    __syncthreads();

    if (threadIdx.x == 0) {
        int right = g_right + s_g;
        float nv = (float)g_valid_cnt;
        float loss = (g_sp_sum + 0.6931471805599453f * (float)(g_valid_cnt - g_gold_cnt)) / nv;
        out[0] = loss;
        out[1] = (float)right / (float)TOPK;
    }
}

// ---------------- launch ----------------
extern "C" void kernel_launch(void* const* d_in, const int* in_sizes, int n_in,
                              void* d_out, int out_size) {
    const float* hidden  = (const float*)d_in[0];
    const float* tw      = (const float*)d_in[1];
    const float* w_in    = (const float*)d_in[2];
    const float* b_in    = (const float*)d_in[3];
    const float* score_w = (const float*)d_in[4];
    const float* score_b = (const float*)d_in[5];
    const int*   seq_len = (const int*)d_in[6];
    const int*   gold    = (const int*)d_in[7];
    float* out = (float*)d_out;

    k_query      <<<Hh / 8, 1024>>>(w_in, tw, b_in);
    k_ef         <<<NTOK / 8, 256>>>(hidden, score_w);
    k_scores     <<<NTOK / 1024, 1024>>>(score_b, seq_len, gold);
    k_count_final<<<CF_BLOCKS, CF_THREADS>>>(out);
}

// round 8
// speedup vs baseline: 1.4446x; 1.1346x over previous
#include <cuda_runtime.h>
#include <cuda_bf16.h>
#include <math.h>

#define Bb 32
#define Ss 512
#define Hh 1024
#define Mm 8
#define NTOK (Bb * Ss)       // 16384
#define NSPAN (NTOK * Mm)    // 131072
#define TOPK 4915            // int(0.3 * B * S)
#define NBIN 65536
#define NCHUNK 1024          // 64 bins per chunk
#define TIE_CAP 16384
#define CF_BLOCKS 148
#define CF_THREADS 256

// ---------------- device scratch ----------------
__device__ float g_query[Hh];
__device__ float g_e[NTOK];
__device__ float g_f[NTOK];
__device__ unsigned int g_keys[NSPAN];
__device__ int   g_hist16[NBIN];
__device__ int   g_chunk[NCHUNK];
__device__ unsigned char g_gbits[NTOK];   // bit l of byte t: span (t,l) valid&&gold
__device__ float g_sp_sum;
__device__ int   g_gold_cnt;
__device__ int   g_valid_cnt;
__device__ unsigned int g_selP;
__device__ int   g_selRem;
__device__ int   g_right;
__device__ int   g_tiecnt;
__device__ int   g_done;      // for k_count_final
__device__ int   g_done_rs;   // for k_reduce_scan last-block
__device__ int   g_tie[TIE_CAP];

__device__ __forceinline__ float warpReduceF(float v) {
    #pragma unroll
    for (int o = 16; o; o >>= 1) v += __shfl_xor_sync(0xffffffffu, v, o);
    return v;
}
__device__ __forceinline__ int warpReduceI(int v) {
    #pragma unroll
    for (int o = 16; o; o >>= 1) v += __shfl_xor_sync(0xffffffffu, v, o);
    return v;
}

// ---------------- kernel 1: query = w_in @ term_weight + b_in; init state ----------------
__global__ void k_query(const float* __restrict__ w_in,
                        const float* __restrict__ tw,
                        const float* __restrict__ b_in) {
    int r = blockIdx.x;
    if (r == 0 && threadIdx.x == 0) {
        g_sp_sum = 0.0f; g_gold_cnt = 0; g_valid_cnt = 0;
        g_right = 0; g_tiecnt = 0; g_done = 0; g_done_rs = 0;
    }
    const float4* wr = reinterpret_cast<const float4*>(w_in + (size_t)r * Hh);
    const float4* t4 = reinterpret_cast<const float4*>(tw);
    int i = threadIdx.x;
    float4 a = wr[i];
    float4 b = t4[i];
    float acc = a.x * b.x + a.y * b.y + a.z * b.z + a.w * b.w;

    __shared__ float sh[8];
    float v = warpReduceF(acc);
    if ((threadIdx.x & 31) == 0) sh[threadIdx.x >> 5] = v;
    __syncthreads();
    if (threadIdx.x < 8) {
        float x = sh[threadIdx.x];
        #pragma unroll
        for (int o = 4; o; o >>= 1) x += __shfl_xor_sync(0xffu, x, o);
        if (threadIdx.x == 0) g_query[r] = x + b_in[r];
    }
}

// ---------------- kernel 2: e/f dot products; also zeroes hist ----------------
__global__ void k_ef(const float* __restrict__ hidden,
                     const float* __restrict__ score_w) {
    __shared__ float shq[Hh];
    __shared__ float shw[Hh];
    int gid = blockIdx.x * blockDim.x + threadIdx.x;
    if (gid < NBIN) g_hist16[gid] = 0;
    for (int i = threadIdx.x; i < Hh; i += blockDim.x) {
        shq[i] = g_query[i];
        shw[i] = score_w[i];
    }
    __syncthreads();

    int warp = threadIdx.x >> 5, lane = threadIdx.x & 31;
    int t = blockIdx.x * 8 + warp;
    const float4* hp = reinterpret_cast<const float4*>(hidden + (size_t)t * Hh);
    float e = 0.0f, f = 0.0f;
    #pragma unroll
    for (int c = 0; c < 8; c++) {
        int j = c * 32 + lane;
        float4 h = hp[j];
        int k = j * 4;
        e += h.x * shq[k] + h.y * shq[k + 1] + h.z * shq[k + 2] + h.w * shq[k + 3];
        f += h.x * shw[k] + h.y * shw[k + 1] + h.z * shw[k + 2] + h.w * shw[k + 3];
    }
    e = warpReduceF(e);
    f = warpReduceF(f);
    if (lane == 0) { g_e[t] = e; g_f[t] = f; }
}

// ---------------- kernel 3: scores, keys, gold bits, loss accum, 16-bit histogram ----------------
__global__ void k_scores(const float* __restrict__ score_b_p,
                         const int* __restrict__ seq_len,
                         const int* __restrict__ gold_mask) {
    int t = blockIdx.x * blockDim.x + threadIdx.x;
    float sp_local = 0.0f;
    int gold_local = 0, valid_local = 0;

    if (t < NTOK) {
        int b = t >> 9, s = t & (Ss - 1);
        int L = seq_len[b];
        float sb = score_b_p[0];

        const int4* gm4 = reinterpret_cast<const int4*>(gold_mask + t * Mm);
        int4 gm0 = gm4[0], gm1 = gm4[1];
        int gm[8] = {gm0.x, gm0.y, gm0.z, gm0.w, gm1.x, gm1.y, gm1.z, gm1.w};

        float m = -INFINITY, den = 0.0f, num = 0.0f;
        unsigned keys[8];
        unsigned char gb = 0;
        #pragma unroll
        for (int l = 0; l < Mm; l++) {
            int pos = s + l; if (pos > Ss - 1) pos = Ss - 1;
            float el = g_e[(b << 9) + pos];
            float fl = g_f[(b << 9) + pos];
            float mn = fmaxf(m, el);
            float sc = expf(m - mn);
            float we = expf(el - mn);
            den = den * sc + we;
            num = num * sc + we * fl;
            m = mn;
            float score = num / den + sb;

            unsigned key;
            if (s + l + 1 <= L) {
                unsigned u = __float_as_uint(score);
                key = u ^ ((u >> 31) ? 0xFFFFFFFFu : 0x80000000u);
                valid_local++;
                if (gm[l] == 0) {
                    gold_local++;
                    gb |= (unsigned char)(1u << l);
                    sp_local += fmaxf(-score, 0.0f) + log1pf(expf(-fabsf(score)));
                }
            } else {
                key = 0x007FFFFFu;  // flipped -inf
            }
            keys[l] = key;
            atomicAdd(&g_hist16[key >> 16], 1);
        }
        uint4* kp = reinterpret_cast<uint4*>(g_keys + t * Mm);
        kp[0] = make_uint4(keys[0], keys[1], keys[2], keys[3]);
        kp[1] = make_uint4(keys[4], keys[5], keys[6], keys[7]);
        g_gbits[t] = gb;
    }

    __shared__ float shf[8];
    __shared__ int shg[8], shv[8];
    float sp = warpReduceF(sp_local);
    int gd = warpReduceI(gold_local);
    int vd = warpReduceI(valid_local);
    if ((threadIdx.x & 31) == 0) {
        int w = threadIdx.x >> 5;
        shf[w] = sp; shg[w] = gd; shv[w] = vd;
    }
    __syncthreads();
    if (threadIdx.x == 0) {
        float S1 = 0.0f; int S2 = 0, S3 = 0;
        #pragma unroll
        for (int w = 0; w < 8; w++) { S1 += shf[w]; S2 += shg[w]; S3 += shv[w]; }
        atomicAdd(&g_sp_sum, S1);
        atomicAdd(&g_gold_cnt, S2);
        atomicAdd(&g_valid_cnt, S3);
    }
}

// ---------------- kernel 4: grid reduce (16 blocks); last block scans + walks boundary ----
__global__ void k_reduce_scan() {
    __shared__ int sch[NCHUNK];
    __shared__ int s_bchunk, s_above;
    __shared__ int s_bins[64];
    __shared__ bool s_last;
    int tid = threadIdx.x;
    int gt = blockIdx.x * 1024 + tid;        // int4 index; covers 4 bins
    const int4* h4 = reinterpret_cast<const int4*>(g_hist16);
    int4 v = h4[gt];                         // fully coalesced
    int sgr = v.x + v.y + v.z + v.w;
    #pragma unroll
    for (int o = 8; o; o >>= 1) sgr += __shfl_xor_sync(0xffffffffu, sgr, o);
    if ((tid & 15) == 0) g_chunk[gt >> 4] = sgr;

    __threadfence();
    __syncthreads();
    if (tid == 0) {
        int d = atomicAdd(&g_done_rs, 1);
        s_last = (d == (int)gridDim.x - 1);
    }
    __syncthreads();
    if (!s_last) return;

    // ---- last block: suffix scan 1024 chunks + staged boundary walk ----
    int csum = g_chunk[tid];                 // hot L2, coalesced 4KB
    sch[tid] = csum;
    __syncthreads();
    for (int off = 1; off < NCHUNK; off <<= 1) {
        int vv = (tid + off < NCHUNK) ? sch[tid + off] : 0;
        __syncthreads();
        sch[tid] += vv;
        __syncthreads();
    }
    int incl = sch[tid];
    int above = incl - csum;
    if (above < TOPK && incl >= TOPK) { s_bchunk = tid; s_above = above; }
    __syncthreads();
    int bc = s_bchunk;
    if (tid < 64) s_bins[tid] = g_hist16[bc * 64 + tid];  // coalesced stage
    __syncthreads();
    if (tid == 0) {
        int cum = s_above;
        for (int b = 63; b >= 0; b--) {
            int c = s_bins[b];
            if (cum + c >= TOPK) {
                g_selP = (unsigned)(bc * 64 + b);
                g_selRem = TOPK - cum;
                break;
            }
            cum += c;
        }
    }
}

// ---------------- kernel 5: count above threshold + ties; last block finalizes ----------------
__global__ void k_count_final(float* __restrict__ out) {
    unsigned P = g_selP;
    int tid = blockIdx.x * blockDim.x + threadIdx.x;
    int nthreads = gridDim.x * blockDim.x;
    int gg = 0;
    for (int i = tid; i < NSPAN; i += nthreads) {
        unsigned top = g_keys[i] >> 16;
        if (top > P) {
            if ((g_gbits[i >> 3] >> (i & 7)) & 1) gg++;
        } else if (top == P) {
            int pos = atomicAdd(&g_tiecnt, 1);
            if (pos < TIE_CAP) g_tie[pos] = i;
        }
    }
    gg = warpReduceI(gg);
    __shared__ int shc[8];
    __shared__ bool s_last;
    if ((threadIdx.x & 31) == 0) shc[threadIdx.x >> 5] = gg;
    __syncthreads();
    if (threadIdx.x == 0) {
        int S = 0;
        #pragma unroll
        for (int w = 0; w < (CF_THREADS >> 5); w++) S += shc[w];
        if (S) atomicAdd(&g_right, S);
        __threadfence();
        int d = atomicAdd(&g_done, 1);
        s_last = (d == (int)gridDim.x - 1);
    }
    __syncthreads();
    if (!s_last) return;

    // ---- final phase: only last block ----
    int n = g_tiecnt; if (n > TIE_CAP) n = TIE_CAP;
    int rem = g_selRem;
    __shared__ int s_g;
    if (threadIdx.x == 0) s_g = 0;
    __syncthreads();

    int gtie = 0;
    for (int j = threadIdx.x; j < n; j += blockDim.x) {
        int ij = g_tie[j];
        unsigned kj = g_keys[ij];
        int rank = 0;
        for (int q = 0; q < n; q++) {
            int iq = g_tie[q];
            unsigned kq = g_keys[iq];
            if (kq > kj || (kq == kj && iq < ij)) rank++;
        }
        if (rank < rem) {
            if ((g_gbits[ij >> 3] >> (ij & 7)) & 1) gtie++;
        }
    }
    gtie = warpReduceI(gtie);
    if ((threadIdx.x & 31) == 0 && gtie) atomicAdd(&s_g, gtie);
    __syncthreads();

    if (threadIdx.x == 0) {
        int right = g_right + s_g;
        float nv = (float)g_valid_cnt;
        float loss = (g_sp_sum + 0.6931471805599453f * (float)(g_valid_cnt - g_gold_cnt)) / nv;
        out[0] = loss;
        out[1] = (float)right / (float)TOPK;
    }
}

// ---------------- launch ----------------
extern "C" void kernel_launch(void* const* d_in, const int* in_sizes, int n_in,
                              void* d_out, int out_size) {
    const float* hidden  = (const float*)d_in[0];
    const float* tw      = (const float*)d_in[1];
    const float* w_in    = (const float*)d_in[2];
    const float* b_in    = (const float*)d_in[3];
    const float* score_w = (const float*)d_in[4];
    const float* score_b = (const float*)d_in[5];
    const int*   seq_len = (const int*)d_in[6];
    const int*   gold    = (const int*)d_in[7];
    float* out = (float*)d_out;

    k_query      <<<Hh, 256>>>(w_in, tw, b_in);
    k_ef         <<<NTOK / 8, 256>>>(hidden, score_w);
    k_scores     <<<NTOK / 256, 256>>>(score_b, seq_len, gold);
    k_reduce_scan<<<16, 1024>>>();
    k_count_final<<<CF_BLOCKS, CF_THREADS>>>(out);
}